// round 9
// baseline (speedup 1.0000x reference)
#include <cuda_runtime.h>

#define NN 50000
#define NE 800000
#define DF 64
#define NF4 16          // DF/4
#define MPOLY 11
#define KD 4            // DEPTH+1
#define SCAN_T 1024

// ---------------- scratch (no allocations allowed) ----------------
__device__ int    g_degi[NN];
__device__ int    g_cursor[NN];
__device__ int    g_off[NN + 1];
__device__ float  g_dinv[NN];
__device__ float2 g_edge[NE];        // {col as int bits, val}
__device__ float4 g_y1[NN * NF4];
__device__ float4 g_y2[NN * NF4];
__device__ float  g_W[KD][KD];

// ---------------- zero deg + cursor ----------------
__global__ void zero_kernel() {
    int i = blockIdx.x * blockDim.x + threadIdx.x;
    if (i < NN) { g_degi[i] = 0; g_cursor[i] = 0; }
}

// ---------------- degree (int atomics) ----------------
__global__ void deg_kernel(const int* __restrict__ row) {
    int e = blockIdx.x * blockDim.x + threadIdx.x;
    if (e < NE) atomicAdd(&g_degi[row[e]], 1);
}

// ---------------- single-block exclusive scan of deg -> off, plus dinv ----------------
__global__ void scan_kernel() {
    __shared__ int s[SCAN_T];
    int t = threadIdx.x;
    const int CH = (NN + SCAN_T - 1) / SCAN_T;   // 49
    int base = t * CH;
    int lim = min(base + CH, NN);

    int local = 0;
    for (int i = base; i < lim; i++) local += g_degi[i];
    s[t] = local;
    __syncthreads();

    // Hillis-Steele inclusive scan
    for (int d = 1; d < SCAN_T; d <<= 1) {
        int v = (t >= d) ? s[t - d] : 0;
        __syncthreads();
        s[t] += v;
        __syncthreads();
    }
    int run = (t == 0) ? 0 : s[t - 1];   // exclusive prefix of this chunk

    for (int i = base; i < lim; i++) {
        g_off[i] = run;
        int d = g_degi[i];
        run += d;
        float df = (d == 0) ? 1.0f : (float)d;
        g_dinv[i] = rsqrtf(df);
    }
    if (t == 0) g_off[NN] = NE;
}

// ---------------- scatter edges into CSR order with fused val ----------------
__global__ void scatter_kernel(const int* __restrict__ row, const int* __restrict__ col,
                               const float* __restrict__ ea) {
    int e = blockIdx.x * blockDim.x + threadIdx.x;
    if (e >= NE) return;
    int r = row[e];
    int c = col[e];
    float v = g_dinv[r] * ea[e] * g_dinv[c];
    int p = g_off[r] + atomicAdd(&g_cursor[r], 1);
    g_edge[p] = make_float2(__int_as_float(c), v);
}

// ---------------- coefficient folding ----------------
__global__ void coeff_kernel(const float* __restrict__ alphas, const float* __restrict__ w,
                             const float* __restrict__ a_arr, const float* __restrict__ b_arr) {
    if (blockIdx.x != 0 || threadIdx.x != 0) return;
    float W[KD][KD];
    for (int k = 0; k < KD; k++)
        for (int j = 0; j < KD; j++) W[k][j] = 0.f;

    for (int m = 0; m < MPOLY; m++) {
        float a = a_arr[m], b = b_arr[m];
        float c[KD][KD];
        for (int k = 0; k < KD; k++)
            for (int j = 0; j < KD; j++) c[k][j] = 0.f;
        c[0][0] = 1.f;

        float al0 = alphas[0 * MPOLY + m];
        c[1][0] = al0 * (a - b) * 0.5f;
        c[1][1] = al0 * (a + b + 2.f) * 0.5f;

        for (int L = 2; L <= 3; L++) {
            float Lf = (float)L;
            float s = a + b;
            float coef_l     = 2.f * Lf * (Lf + s) * (2.f * Lf - 2.f + s);
            float coef_lm1_1 = (2.f * Lf + s - 1.f) * (2.f * Lf + s) * (2.f * Lf + s - 2.f);
            float coef_lm1_2 = (2.f * Lf + s - 1.f) * (a * a - b * b);
            float coef_lm2   = 2.f * (Lf - 1.f + a) * (Lf - 1.f + b) * (2.f * Lf + s);
            float alL   = alphas[(L - 1) * MPOLY + m];
            float alLm1 = alphas[(L - 2) * MPOLY + m];
            float tmp1 = alL * (coef_lm1_1 / coef_l);
            float tmp2 = alL * (coef_lm1_2 / coef_l);
            float tmp3 = alL * alLm1 * (coef_lm2 / coef_l);
            for (int j = 0; j < KD; j++)
                c[L][j] = -tmp2 * c[L - 1][j] - tmp3 * c[L - 2][j];
            for (int j = 0; j < KD - 1; j++)
                c[L][j + 1] += tmp1 * c[L - 1][j];
        }
        float wm = w[m];
        for (int k = 0; k < KD; k++)
            for (int j = 0; j < KD; j++) W[k][j] += wm * c[k][j];
    }
    for (int k = 0; k < KD; k++)
        for (int j = 0; j < KD; j++) g_W[k][j] = W[k][j];
}

// ---------------- CSR SpMM stages 1,2: 16 threads per row, no atomics ----------------
template <int STAGE>
__global__ void __launch_bounds__(256) spmm_csr_kernel(const float4* __restrict__ xext) {
    int tid = blockIdx.x * blockDim.x + threadIdx.x;   // NN*16 threads exactly
    int r = tid >> 4;
    int f = tid & 15;
    const float4* __restrict__ xin = (STAGE == 1) ? xext : (const float4*)g_y1;
    float4* yout = (STAGE == 1) ? g_y1 : g_y2;

    int e   = g_off[r];
    int end = g_off[r + 1];
    float4 acc = make_float4(0.f, 0.f, 0.f, 0.f);
#pragma unroll 4
    for (; e < end; e++) {
        float2 cv = __ldg(&g_edge[e]);
        int   c = __float_as_int(cv.x);
        float v = cv.y;
        float4 xv = __ldg(&xin[c * NF4 + f]);
        acc.x += v * xv.x;
        acc.y += v * xv.y;
        acc.z += v * xv.z;
        acc.w += v * xv.w;
    }
    yout[r * NF4 + f] = acc;
}

// ---------------- stage 3 SpMM fused with combine epilogue ----------------
// acc = (S^3 x)[r][f]; out[r][k][f] = W[k][0]*x + W[k][1]*y1 + W[k][2]*y2 + W[k][3]*acc
__global__ void __launch_bounds__(256) spmm3_combine_kernel(const float4* __restrict__ x,
                                                            float4* __restrict__ out) {
    int tid = blockIdx.x * blockDim.x + threadIdx.x;   // NN*16 threads exactly
    int r = tid >> 4;
    int f = tid & 15;

    int e   = g_off[r];
    int end = g_off[r + 1];
    float4 acc = make_float4(0.f, 0.f, 0.f, 0.f);
#pragma unroll 4
    for (; e < end; e++) {
        float2 cv = __ldg(&g_edge[e]);
        int   c = __float_as_int(cv.x);
        float v = cv.y;
        float4 xv = __ldg(&g_y2[c * NF4 + f]);
        acc.x += v * xv.x;
        acc.y += v * xv.y;
        acc.z += v * xv.z;
        acc.w += v * xv.w;
    }

    int idx = r * NF4 + f;
    float4 h0 = __ldg(&x[idx]);
    float4 h1 = g_y1[idx];
    float4 h2 = g_y2[idx];
#pragma unroll
    for (int k = 0; k < KD; k++) {
        float w0 = g_W[k][0], w1 = g_W[k][1], w2 = g_W[k][2], w3 = g_W[k][3];
        float4 o;
        o.x = w0 * h0.x + w1 * h1.x + w2 * h2.x + w3 * acc.x;
        o.y = w0 * h0.y + w1 * h1.y + w2 * h2.y + w3 * acc.y;
        o.z = w0 * h0.z + w1 * h1.z + w2 * h2.z + w3 * acc.z;
        o.w = w0 * h0.w + w1 * h1.w + w2 * h2.w + w3 * acc.w;
        out[(r * KD + k) * NF4 + f] = o;
    }
}

// ---------------- launch ----------------
extern "C" void kernel_launch(void* const* d_in, const int* in_sizes, int n_in,
                              void* d_out, int out_size) {
    const float* x      = (const float*)d_in[0];
    const int*   ei     = (const int*)d_in[1];
    const float* ea     = (const float*)d_in[2];
    const float* alphas = (const float*)d_in[3];
    const float* w      = (const float*)d_in[4];
    const float* a_arr  = (const float*)d_in[5];
    const float* b_arr  = (const float*)d_in[6];
    const int* row = ei;
    const int* col = ei + NE;

    zero_kernel<<<(NN + 255) / 256, 256>>>();
    deg_kernel<<<(NE + 255) / 256, 256>>>(row);
    scan_kernel<<<1, SCAN_T>>>();
    scatter_kernel<<<(NE + 255) / 256, 256>>>(row, col, ea);
    coeff_kernel<<<1, 32>>>(alphas, w, a_arr, b_arr);

    const float4* x4 = (const float4*)x;
    spmm_csr_kernel<1><<<(NN * 16) / 256, 256>>>(x4);   // 3125 blocks
    spmm_csr_kernel<2><<<(NN * 16) / 256, 256>>>(x4);
    spmm3_combine_kernel<<<(NN * 16) / 256, 256>>>(x4, (float4*)d_out);
}